// round 12
// baseline (speedup 1.0000x reference)
#include <cuda_runtime.h>
#include <cuda_fp16.h>
#include <cstdint>

// ============================================================================
// BatchConv2D 3x3 via mma.sync f16 (2-term: x_fp16 * (wh + wl)), fp32 accum.
// CTA = 256 thr (8 warps): (batch, x-half 128px, 8 rows), all 32 oc.
// 4 steps x 2 rows; warp = one row x 32px x 32oc (m32n32). K = 288 per term.
// NEW: next step's 2 input rows are prefetched into a raw fp32 SMEM buffer via
// cp.async DURING the MMA block; after the post-MMA sync a short SMEM->SMEM
// convert pass packs them into the fp16 ring. Global latency is hidden.
// ============================================================================

#define BATCH 32
#define CH    32
#define HH    256
#define WW    256
#define HW    (HH * WW)

#define A_STR   136                 // u32 per (slot,j) row; 136 % 32 == 8
#define SLOT_W  (16 * A_STR)        // 2176 u32 per row slot
#define WQ_STR  148                 // uint2 per oc; 148 % 16 == 4

#define SMEM_BIAS 0                                   // 128 B
#define SMEM_WQ   128                                 // 32*148*8 = 37888 B
#define SMEM_RING (SMEM_WQ + 37888)                   // 38016
#define SMEM_RAW  (SMEM_RING + 4 * SLOT_W * 4)        // 72832
// raw: [2 rows][16 pair][132 px][2 floats] = 33792 B
#define SMEM_TOTAL (SMEM_RAW + 2 * 16 * 132 * 2 * 4)  // 106624 B

__device__ __forceinline__ void mma_f16(float* d, const uint32_t* a,
                                        uint32_t b0, uint32_t b1) {
    asm volatile(
        "mma.sync.aligned.m16n8k16.row.col.f32.f16.f16.f32 "
        "{%0,%1,%2,%3}, {%4,%5,%6,%7}, {%8,%9}, {%0,%1,%2,%3};\n"
        : "+f"(d[0]), "+f"(d[1]), "+f"(d[2]), "+f"(d[3])
        : "r"(a[0]), "r"(a[1]), "r"(a[2]), "r"(a[3]), "r"(b0), "r"(b1));
}

__device__ __forceinline__ void cp_async4(uint32_t dst, const void* src,
                                          int src_sz) {
    asm volatile("cp.async.ca.shared.global [%0], [%1], 4, %2;"
                 :: "r"(dst), "l"(src), "r"(src_sz));
}
__device__ __forceinline__ void cp_async_commit() {
    asm volatile("cp.async.commit_group;" ::: "memory");
}
__device__ __forceinline__ void cp_async_wait0() {
    asm volatile("cp.async.wait_group 0;" ::: "memory");
}

// Synchronous stage (initial fill only).
__device__ __forceinline__ void stage_row(uint32_t* ring,
                                          const float* __restrict__ xb,
                                          int gy, int x0, int tid) {
    uint32_t* rs = ring + ((gy + 4) & 3) * SLOT_W;
    const bool yok = (unsigned)gy < (unsigned)HH;
    const float* rowp = xb + (size_t)(yok ? gy : 0) * WW;
    for (int idx = tid; idx < 16 * 130; idx += 256) {
        const int j = idx / 130;
        const int i = idx - j * 130;
        const int gx = x0 - 1 + i;
        const bool ok = yok && ((unsigned)gx < (unsigned)WW);
        const float* px = rowp + (ok ? gx : 0);
        const float v0 = ok ? px[(2 * j) * HW] : 0.0f;
        const float v1 = ok ? px[(2 * j + 1) * HW] : 0.0f;
        const __half2 h2 = __floats2half2_rn(v0, v1);
        rs[j * A_STR + i] = *reinterpret_cast<const uint32_t*>(&h2);
    }
}

__global__ void __launch_bounds__(256, 2)
batch_conv3x3_f16p_kernel(const float* __restrict__ x,
                          const float* __restrict__ w,
                          const float* __restrict__ bias,
                          float* __restrict__ out)
{
    extern __shared__ char smem[];
    float*    bias_s = reinterpret_cast<float*>(smem + SMEM_BIAS);
    uint2*    wq     = reinterpret_cast<uint2*>(smem + SMEM_WQ);
    uint32_t* ring   = reinterpret_cast<uint32_t*>(smem + SMEM_RING);
    float*    raw_f  = reinterpret_cast<float*>(smem + SMEM_RAW);

    uint32_t smem_base;
    asm("{ .reg .u64 t; cvta.to.shared.u64 t, %1; cvt.u32.u64 %0, t; }"
        : "=r"(smem_base) : "l"(smem));
    const uint32_t raw_base = smem_base + SMEM_RAW;

    const int tid  = threadIdx.x;       // 0..255
    const int lane = tid & 31;
    const int wid  = tid >> 5;          // 0..7
    const int xh   = blockIdx.x;        // 0..1
    const int yg   = blockIdx.y;        // 0..31
    const int b    = blockIdx.z;        // 0..31
    const int x0   = xh * 128;
    const int y0   = yg * 8;

    if (tid < CH) bias_s[tid] = bias[b * CH + tid];

    // ---- weights -> SMEM: wq[oc*WQ_STR + tap*16 + kp] = (hi_pair, lo_pair)
    const float* wg = w + (size_t)b * (CH * CH * 9);
    for (int idx = tid; idx < CH * 9 * 16; idx += 256) {
        const int oc  = idx / 144;
        const int rem = idx - oc * 144;
        const int tap = rem >> 4;
        const int kp  = rem & 15;
        const float v0 = wg[(oc * CH + 2 * kp) * 9 + tap];
        const float v1 = wg[(oc * CH + 2 * kp + 1) * 9 + tap];
        const __half h0 = __float2half_rn(v0);
        const __half h1 = __float2half_rn(v1);
        const __half l0 = __float2half_rn(v0 - __half2float(h0));
        const __half l1 = __float2half_rn(v1 - __half2float(h1));
        const uint32_t hiw =
            ((uint32_t)__half_as_ushort(h1) << 16) | __half_as_ushort(h0);
        const uint32_t low =
            ((uint32_t)__half_as_ushort(l1) << 16) | __half_as_ushort(l0);
        wq[oc * WQ_STR + rem] = make_uint2(hiw, low);
    }

    // ---- initial ring fill: input rows y0-1 .. y0+2 (synchronous)
    const float* xb = x + (size_t)b * CH * HW;
    stage_row(ring, xb, y0 - 1, x0, tid);
    stage_row(ring, xb, y0,     x0, tid);
    stage_row(ring, xb, y0 + 1, x0, tid);
    stage_row(ring, xb, y0 + 2, x0, tid);
    __syncthreads();

    const int g    = lane >> 2;        // 0..7
    const int tg   = lane & 3;         // 0..3
    const int p0   = (wid & 3) * 32;   // pixel base within 128
    const int rsel = wid >> 2;         // 0/1: row within the pair

#pragma unroll 1
    for (int s = 0; s < 4; ++s) {
        const int row = y0 + 2 * s + rsel;

        // ---- prefetch next 2 input rows into raw buffer (async, no wait)
        if (s < 3) {
            const int gy0 = y0 + 2 * s + 3;
            for (int e = tid; e < 2 * CH * 130; e += 256) {
                const int r   = e / (CH * 130);
                const int rem = e - r * (CH * 130);
                const int c   = rem / 130;
                const int i   = rem - c * 130;
                const int gy  = gy0 + r;
                const int gx  = x0 - 1 + i;
                const bool ok = (gy < HH) && ((unsigned)gx < (unsigned)WW);
                const float* src = xb + (size_t)c * HW +
                                   (size_t)(ok ? gy : 0) * WW + (ok ? gx : 0);
                const uint32_t dst = raw_base +
                    ((((r * 16 + (c >> 1)) * 132 + i) << 1) | (c & 1)) * 4;
                cp_async4(dst, src, ok ? 4 : 0);
            }
            cp_async_commit();
        }

        float acc[2][4][4];
#pragma unroll
        for (int nb = 0; nb < 4; ++nb) {
            const float b0v = bias_s[nb * 8 + tg * 2];
            const float b1v = bias_s[nb * 8 + tg * 2 + 1];
#pragma unroll
            for (int t = 0; t < 2; ++t) {
                acc[t][nb][0] = b0v; acc[t][nb][1] = b1v;
                acc[t][nb][2] = b0v; acc[t][nb][3] = b1v;
            }
        }

#pragma unroll
        for (int tap = 0; tap < 9; ++tap) {
            const int dy = tap / 3, dx = tap % 3;
            const uint32_t* rs = ring + ((row - 1 + dy + 4) & 3) * SLOT_W;
#pragma unroll
            for (int half = 0; half < 2; ++half) {
                const int rj  = (half * 8 + tg) * A_STR;
                const int rj4 = rj + 4 * A_STR;
                uint32_t a[2][4];
#pragma unroll
                for (int t = 0; t < 2; ++t) {
                    const int pb = p0 + t * 16 + g + dx;
                    a[t][0] = rs[rj + pb];   a[t][1] = rs[rj + pb + 8];
                    a[t][2] = rs[rj4 + pb];  a[t][3] = rs[rj4 + pb + 8];
                }
                const int wbse = tap * 16 + half * 8 + tg;
                uint2 q0[4], q1[4];
#pragma unroll
                for (int nb = 0; nb < 4; ++nb) {
                    const int base = (nb * 8 + g) * WQ_STR + wbse;
                    q0[nb] = wq[base];
                    q1[nb] = wq[base + 4];
                }
#pragma unroll
                for (int nb = 0; nb < 4; ++nb) {
                    mma_f16(acc[0][nb], a[0], q0[nb].x, q1[nb].x);
                    mma_f16(acc[1][nb], a[1], q0[nb].x, q1[nb].x);
                }
#pragma unroll
                for (int nb = 0; nb < 4; ++nb) {
                    mma_f16(acc[0][nb], a[0], q0[nb].y, q1[nb].y);
                    mma_f16(acc[1][nb], a[1], q0[nb].y, q1[nb].y);
                }
            }
        }

        // ---- store this row's 32px x 32oc tile
        float* ob = out + (size_t)b * CH * HW + (size_t)row * WW + x0;
#pragma unroll
        for (int t = 0; t < 2; ++t) {
            const int p = p0 + t * 16 + g;
#pragma unroll
            for (int nb = 0; nb < 4; ++nb) {
                const int oc0 = nb * 8 + tg * 2;
                ob[(size_t)oc0 * HW + p]           = acc[t][nb][0];
                ob[(size_t)(oc0 + 1) * HW + p]     = acc[t][nb][1];
                ob[(size_t)oc0 * HW + p + 8]       = acc[t][nb][2];
                ob[(size_t)(oc0 + 1) * HW + p + 8] = acc[t][nb][3];
            }
        }

        // ---- ring advance: convert prefetched raw rows -> fp16 ring
        __syncthreads();
        if (s < 3) {
            cp_async_wait0();
            const int gy0 = y0 + 2 * s + 3;
            for (int idx = tid; idx < 2 * 16 * 130; idx += 256) {
                const int r   = idx / (16 * 130);
                const int rem = idx - r * (16 * 130);
                const int j   = rem / 130;
                const int i   = rem - j * 130;
                const float2 v = *reinterpret_cast<const float2*>(
                    raw_f + (((r * 16 + j) * 132 + i) << 1));
                const __half2 h2 = __floats2half2_rn(v.x, v.y);
                ring[((gy0 + r + 4) & 3) * SLOT_W + j * A_STR + i] =
                    *reinterpret_cast<const uint32_t*>(&h2);
            }
            __syncthreads();
        }
    }
}

extern "C" void kernel_launch(void* const* d_in, const int* in_sizes, int n_in,
                              void* d_out, int out_size)
{
    const float* x    = (const float*)d_in[0];
    const float* w    = (const float*)d_in[1];
    const float* bias = (const float*)d_in[2];
    float* out        = (float*)d_out;

    cudaFuncSetAttribute(batch_conv3x3_f16p_kernel,
                         cudaFuncAttributeMaxDynamicSharedMemorySize,
                         SMEM_TOTAL);

    dim3 grid(2, HH / 8, BATCH);   // 2048 CTAs
    batch_conv3x3_f16p_kernel<<<grid, 256, SMEM_TOTAL>>>(x, w, bias, out);
}